// round 17
// baseline (speedup 1.0000x reference)
#include <cuda_runtime.h>
#include <cuda_fp16.h>
#include <math.h>

// ---------------- problem constants ----------------
static const int NTOK   = 8192;   // N
static const int DMODEL = 512;    // D
static const int NHEADS = 8;
static const int DHEAD  = 64;
static const int MLAND  = 256;    // M landmarks
static const int LFOLD  = 32;     // N / M
static const int WPD    = 256;    // weight_params_dim
static const int NEDGE  = 262144; // E
static const int KCONV  = 33;
static const int QKVW   = 3 * NHEADS * DHEAD; // 1536
static const int PITERS = 6;

// ---------------- device scratch (BSS) ----------------
__device__ float g_qkv [NTOK * QKVW];
__device__ float g_ql  [NHEADS * MLAND * DHEAD];
__device__ float g_kl  [NHEADS * MLAND * DHEAD];
__device__ float g_a1  [(long)NHEADS * NTOK * MLAND];
__device__ float g_a2  [NHEADS * MLAND * MLAND];
__device__ float g_a3  [(long)NHEADS * MLAND * NTOK];
__device__ float g_z   [NHEADS * MLAND * MLAND];
__device__ float g_zT  [NHEADS * MLAND * MLAND];
__device__ float g_z2  [NHEADS * MLAND * MLAND];
__device__ float g_z2T [NHEADS * MLAND * MLAND];
__device__ float g_xz  [NHEADS * MLAND * MLAND];
__device__ float g_t1  [NHEADS * MLAND * MLAND];
__device__ float g_t1T [NHEADS * MLAND * MLAND];
__device__ float g_t2  [NHEADS * MLAND * MLAND];
__device__ float g_t2T [NHEADS * MLAND * MLAND];
__device__ float g_a3v [NHEADS * MLAND * DHEAD];
__device__ float g_zv  [NHEADS * MLAND * DHEAD];
__device__ float g_xh  [NTOK * DMODEL];
__device__ float g_enc [NTOK * DMODEL];
__device__ float g_qeke [NTOK * 2 * WPD];
__device__ float g_wqkT [2 * WPD * DMODEL];
__device__ float g_rs1 [NHEADS * NTOK];   // a1 exp row sums
__device__ float g_rs3 [NHEADS * MLAND];  // a3 exp row sums
__device__ float g_Araw [NTOK];
__device__ float g_alpha[NTOK];
__device__ unsigned int g_norm[2];

// ---------------- ptx helpers ----------------
__device__ __forceinline__ unsigned sptr(const void* p) {
    return (unsigned)__cvta_generic_to_shared(p);
}
__device__ __forceinline__ void ldsm4(unsigned& r0, unsigned& r1, unsigned& r2,
                                      unsigned& r3, unsigned addr) {
    asm volatile("ldmatrix.sync.aligned.m8n8.x4.shared.b16 {%0,%1,%2,%3}, [%4];"
        : "=r"(r0), "=r"(r1), "=r"(r2), "=r"(r3) : "r"(addr));
}
__device__ __forceinline__ void mma16(float* c, const unsigned* a, const unsigned* b) {
    asm volatile(
        "mma.sync.aligned.m16n8k16.row.col.f32.f16.f16.f32 "
        "{%0,%1,%2,%3}, {%4,%5,%6,%7}, {%8,%9}, {%0,%1,%2,%3};"
        : "+f"(c[0]), "+f"(c[1]), "+f"(c[2]), "+f"(c[3])
        : "r"(a[0]), "r"(a[1]), "r"(a[2]), "r"(a[3]), "r"(b[0]), "r"(b[1]));
}

// split 8 fp32 -> 8 f16 hi-plane + 8 f16 residual-plane (packed uint4 each)
__device__ __forceinline__ void packsplit8(const float4& v0, const float4& v1,
                                           uint4& h, uint4& r)
{
    float v[8];
    *(float4*)v       = v0;
    *(float4*)(v + 4) = v1;
    unsigned hh[4], rr[4];
    #pragma unroll
    for (int i = 0; i < 4; i++) {
        __half2 p = __floats2half2_rn(v[2 * i], v[2 * i + 1]);
        hh[i] = *(unsigned*)&p;
        float lo = __half2float(__low2half(p));
        float hi = __half2float(__high2half(p));
        __half2 q = __floats2half2_rn(v[2 * i] - lo, v[2 * i + 1] - hi);
        rr[i] = *(unsigned*)&q;
    }
    h = make_uint4(hh[0], hh[1], hh[2], hh[3]);
    r = make_uint4(rr[0], rr[1], rr[2], rr[3]);
}

// =====================================================================
// gemmH: fp16x2 tensor GEMM (h/r split, 3 passes of m16n8k16).
// C = alpha * A[M,K] @ B^T (+addC +bias); optional exp epilogue with
// per-row sums (atomicAdd); optional gated-blend final epilogue (alphaV).
// B stored [N,K] (TB form). CTA 128x128, 128 thr = 4 warps, warp 64x64.
// =====================================================================
static const int HROWB  = 48;
static const int HPLANE = 128 * HROWB;   // 6144 B
static const int HBUF   = 4 * HPLANE;    // 24576 B
__global__ __launch_bounds__(128, 2)
void gemmH_k(int M, int N, int K, float alpha,
             const float* __restrict__ A, int lda, long sA,
             const float* __restrict__ B, int ldb, long sB,
             float* __restrict__ C, int ldc, long sC,
             const float* __restrict__ addC, const float* __restrict__ bias,
             int doExp, float* __restrict__ rowsum,
             const float* __restrict__ alphaV)
{
    __shared__ __align__(16) char smem[2 * HBUF];

    A += (long)blockIdx.z * sA;
    B += (long)blockIdx.z * sB;
    C += (long)blockIdx.z * sC;
    if (addC)   addC   += (long)blockIdx.z * sC;
    if (rowsum) rowsum += (long)blockIdx.z * M;

    const int row0 = blockIdx.y * 128;
    const int col0 = blockIdx.x * 128;
    const int tid  = threadIdx.x;
    const int lane = tid & 31, w = tid >> 5, wr = w >> 1, wc = w & 1;

    const float* aSrc = A + (long)(row0 + tid) * lda;
    const float* bSrc = B + (long)(col0 + tid) * ldb;

    const unsigned offA = tid * HROWB;
    const unsigned offB = 2 * HPLANE + tid * HROWB;

    unsigned aLd[4];
    #pragma unroll
    for (int rt = 0; rt < 4; rt++) {
        int rrow = wr * 64 + rt * 16 + (lane & 15);
        aLd[rt] = sptr(smem + rrow * HROWB + (lane >> 4) * 16);
    }
    unsigned bLd[4];
    #pragma unroll
    for (int p = 0; p < 4; p++) {
        int n = wc * 64 + p * 16 + (lane & 7) + ((lane & 16) >> 1);
        bLd[p] = sptr(smem + 2 * HPLANE + n * HROWB + ((lane >> 3) & 1) * 16);
    }

    float acc[4][8][4];
    #pragma unroll
    for (int i = 0; i < 4; i++)
        #pragma unroll
        for (int j = 0; j < 8; j++)
            #pragma unroll
            for (int v = 0; v < 4; v++) acc[i][j][v] = 0.f;

    const int CH = K >> 4;
    float4 pa0, pa1, pa2, pa3, pb0, pb1, pb2, pb3;
    auto loadRegs = [&](int c) {
        const float* a = aSrc + c * 16;
        const float* b = bSrc + c * 16;
        pa0 = *(const float4*)(a);      pa1 = *(const float4*)(a + 4);
        pa2 = *(const float4*)(a + 8);  pa3 = *(const float4*)(a + 12);
        pb0 = *(const float4*)(b);      pb1 = *(const float4*)(b + 4);
        pb2 = *(const float4*)(b + 8);  pb3 = *(const float4*)(b + 12);
    };
    auto stsAll = [&](int b) {
        unsigned off = b * HBUF;
        uint4 h, r;
        packsplit8(pa0, pa1, h, r);
        *(uint4*)(smem + offA + off)               = h;
        *(uint4*)(smem + offA + off + HPLANE)      = r;
        packsplit8(pa2, pa3, h, r);
        *(uint4*)(smem + offA + off + 16)          = h;
        *(uint4*)(smem + offA + off + HPLANE + 16) = r;
        packsplit8(pb0, pb1, h, r);
        *(uint4*)(smem + offB + off)               = h;
        *(uint4*)(smem + offB + off + HPLANE)      = r;
        packsplit8(pb2, pb3, h, r);
        *(uint4*)(smem + offB + off + 16)          = h;
        *(uint4*)(smem + offB + off + HPLANE + 16) = r;
    };

    loadRegs(0);
    for (int c = 0; c < CH; c++) {
        int b = c & 1;
        stsAll(b);
        if (c + 1 < CH) loadRegs(c + 1);
        __syncthreads();
        unsigned off = b * HBUF;
        unsigned ah[4][4], ar[4][4];
        #pragma unroll
        for (int rt = 0; rt < 4; rt++) {
            ldsm4(ah[rt][0], ah[rt][1], ah[rt][2], ah[rt][3], aLd[rt] + off);
            ldsm4(ar[rt][0], ar[rt][1], ar[rt][2], ar[rt][3],
                  aLd[rt] + off + HPLANE);
        }
        #pragma unroll
        for (int p = 0; p < 4; p++) {
            unsigned bh[4], br[4];
            ldsm4(bh[0], bh[1], bh[2], bh[3], bLd[p] + off);
            ldsm4(br[0], br[1], br[2], br[3], bLd[p] + off + HPLANE);
            #pragma unroll
            for (int rt = 0; rt < 4; rt++) {
                mma16(acc[rt][2 * p],     ah[rt], bh);
                mma16(acc[rt][2 * p],     ah[rt], br);
                mma16(acc[rt][2 * p],     ar[rt], bh);
                mma16(acc[rt][2 * p + 1], ah[rt], bh + 2);
                mma16(acc[rt][2 * p + 1], ah[rt], br + 2);
                mma16(acc[rt][2 * p + 1], ar[rt], bh + 2);
            }
        }
    }

    const int g = lane >> 2, tg = lane & 3;
    #pragma unroll
    for (int rt = 0; rt < 4; rt++) {
        float rsum0 = 0.f, rsum1 = 0.f;
        #pragma unroll
        for (int n2 = 0; n2 < 8; n2++) {
            int gr = row0 + wr * 64 + rt * 16 + g;
            int gc = col0 + wc * 64 + n2 * 8 + tg * 2;
            float* c = acc[rt][n2];
            long i0 = (long)gr * ldc + gc;
            long i1 = i0 + 8 * (long)ldc;
            float v00 = alpha * c[0], v01 = alpha * c[1];
            float v10 = alpha * c[2], v11 = alpha * c[3];
            if (addC && !alphaV) {
                v00 += addC[i0]; v01 += addC[i0 + 1];
                v10 += addC[i1]; v11 += addC[i1 + 1];
            }
            if (bias) {
                v00 += bias[gc]; v01 += bias[gc + 1];
                v10 += bias[gc]; v11 += bias[gc + 1];
            }
            if (doExp) {
                v00 = __expf(v00); v01 = __expf(v01);
                v10 = __expf(v10); v11 = __expf(v11);
            }
            if (alphaV) {
                // gated final blend: xl = alphaV[row]*v; w = sigmoid(-xl);
                // out = 2*xl*w^2 + 2*enc*(1-w^2)   (enc passed as addC)
                float al0 = alphaV[gr], al1 = alphaV[gr + 8];
                float xl, ws, sq;
                xl = al0 * v00; ws = 1.f / (1.f + __expf(xl)); sq = ws * ws;
                v00 = xl * 2.f * sq + 2.f * addC[i0] * (1.f - sq);
                xl = al0 * v01; ws = 1.f / (1.f + __expf(xl)); sq = ws * ws;
                v01 = xl * 2.f * sq + 2.f * addC[i0 + 1] * (1.f - sq);
                xl = al1 * v10; ws = 1.f / (1.f + __expf(xl)); sq = ws * ws;
                v10 = xl * 2.f * sq + 2.f * addC[i1] * (1.f - sq);
                xl = al1 * v11; ws = 1.f / (1.f + __expf(xl)); sq = ws * ws;
                v11 = xl * 2.f * sq + 2.f * addC[i1 + 1] * (1.f - sq);
            }
            C[i0] = v00; C[i0 + 1] = v01;
            C[i1] = v10; C[i1 + 1] = v11;
            rsum0 += v00 + v01;
            rsum1 += v10 + v11;
        }
        if (rowsum) {
            rsum0 += __shfl_xor_sync(0xffffffffu, rsum0, 1);
            rsum0 += __shfl_xor_sync(0xffffffffu, rsum0, 2);
            rsum1 += __shfl_xor_sync(0xffffffffu, rsum1, 1);
            rsum1 += __shfl_xor_sync(0xffffffffu, rsum1, 2);
            if (tg == 0) {
                int gr = row0 + wr * 64 + rt * 16 + g;
                atomicAdd(&rowsum[gr], rsum0);
                atomicAdd(&rowsum[gr + 8], rsum1);
            }
        }
    }
}

static void gemmH(int M, int N, int K, float alpha,
                  const float* A, int lda, long sA,
                  const float* B, int ldb, long sB,
                  float* C, int ldc, long sC, int batch,
                  const float* addC = nullptr, const float* bias = nullptr,
                  int doExp = 0, float* rowsum = nullptr,
                  const float* alphaV = nullptr)
{
    dim3 g(N / 128, M / 128, batch);
    gemmH_k<<<g, 128>>>(M, N, K, alpha, A, lda, sA, B, ldb, sB,
                        C, ldc, sC, addC, bias, doExp, rowsum, alphaV);
}

// =====================================================================
// gemmH64: fp16x2 GEMM, CTA tile 128x64, NT form (B = [K,N] row-major).
// Optional per-B-row divide by brs[row] (folded softmax normalization).
// 128 threads = 4 warps (4x1), warp tile 32x64. Optional split-K atomic.
// =====================================================================
static const int QROWB   = 48;
static const int QAPLANE = 128 * QROWB;
static const int QBPLANE = 64 * QROWB;
static const int QBUF    = 2 * QAPLANE + 2 * QBPLANE;
__global__ __launch_bounds__(128, 3)
void gemmH64_k(int M, int K, float alpha,
               const float* __restrict__ A, int lda, long sA,
               const float* __restrict__ B, int ldb, long sB,
               float* __restrict__ C, int ldc, long sC, int kSplit,
               const float* __restrict__ brs)
{
    __shared__ __align__(16) char smem[2 * QBUF];

    int bz = blockIdx.z;
    int batch = bz / kSplit, ks = bz - batch * kSplit;
    A += (long)batch * sA; B += (long)batch * sB; C += (long)batch * sC;
    const int chunk = K / kSplit;
    const int k0s = ks * chunk;
    const int CH = chunk >> 4;

    const int row0 = blockIdx.y * 128;
    const int tid  = threadIdx.x;
    const int lane = tid & 31, w = tid >> 5;

    const float* aSrc = A + (long)(row0 + tid) * lda + k0s;
    const unsigned offA = tid * QROWB;
    const int bn = tid & 63, bkh = (tid >> 6) * 8;
    const float* bSrc = B + (long)(k0s + bkh) * ldb + bn;
    const float* brsRow = brs ? (brs + (long)batch * K + k0s + bkh) : nullptr;
    const unsigned offB = 2 * QAPLANE + bn * QROWB + bkh * 2;

    unsigned aLd[2];
    #pragma unroll
    for (int rt = 0; rt < 2; rt++) {
        int rrow = w * 32 + rt * 16 + (lane & 15);
        aLd[rt] = sptr(smem + rrow * QROWB + (lane >> 4) * 16);
    }
    unsigned bLd[4];
    #pragma unroll
    for (int p = 0; p < 4; p++) {
        int n = p * 16 + (lane & 7) + ((lane & 16) >> 1);
        bLd[p] = sptr(smem + 2 * QAPLANE + n * QROWB + ((lane >> 3) & 1) * 16);
    }

    float acc[2][8][4];
    #pragma unroll
    for (int i = 0; i < 2; i++)
        #pragma unroll
        for (int j = 0; j < 8; j++)
            #pragma unroll
            for (int v = 0; v < 4; v++) acc[i][j][v] = 0.f;

    float4 pa0, pa1, pa2, pa3;
    float vb[8];
    auto loadRegs = [&](int c) {
        const float* a = aSrc + c * 16;
        pa0 = *(const float4*)(a);      pa1 = *(const float4*)(a + 4);
        pa2 = *(const float4*)(a + 8);  pa3 = *(const float4*)(a + 12);
        const float* b = bSrc + (long)c * 16 * ldb;
        #pragma unroll
        for (int j = 0; j < 8; j++) vb[j] = b[(long)j * ldb];
        if (brsRow) {
            const float* s = brsRow + c * 16;
            #pragma unroll
            for (int j = 0; j < 8; j++) vb[j] /= s[j];
        }
    };
    auto stsAll = [&](int b) {
        unsigned off = b * QBUF;
        uint4 h, r;
        packsplit8(pa0, pa1, h, r);
        *(uint4*)(smem + offA + off)                = h;
        *(uint4*)(smem + offA + off + QAPLANE)      = r;
        packsplit8(pa2, pa3, h, r);
        *(uint4*)(smem + offA + off + 16)           = h;
        *(uint4*)(smem + offA + off + QAPLANE + 16) = r;
        packsplit8(make_float4(vb[0], vb[1], vb[2], vb[3]),
                   make_float4(vb[4], vb[5], vb[6], vb[7]), h, r);
        *(uint4*)(smem + offB + off)                = h;
        *(uint4*)(smem + offB + off + QBPLANE)      = r;
    };

    loadRegs(0);
    for (int c = 0; c < CH; c++) {
        int b = c & 1;
        stsAll(b);
        if (c + 1 < CH) loadRegs(c + 1);
        __syncthreads();
        unsigned off = b * QBUF;
        unsigned ah[2][4], ar[2][4];
        #pragma unroll
        for (int rt = 0; rt < 2; rt++) {
            ldsm4(ah[rt][0], ah[rt][1], ah[rt][2], ah[rt][3], aLd[rt] + off);
            ldsm4(ar[rt][0], ar[rt][1], ar[rt][2], ar[rt][3],
                  aLd[rt] + off + QAPLANE);
        }
        #pragma unroll
        for (int p = 0; p < 4; p++) {
            unsigned bh[4], br[4];
            ldsm4(bh[0], bh[1], bh[2], bh[3], bLd[p] + off);
            ldsm4(br[0], br[1], br[2], br[3], bLd[p] + off + QBPLANE);
            #pragma unroll
            for (int rt = 0; rt < 2; rt++) {
                mma16(acc[rt][2 * p],     ah[rt], bh);
                mma16(acc[rt][2 * p],     ah[rt], br);
                mma16(acc[rt][2 * p],     ar[rt], bh);
                mma16(acc[rt][2 * p + 1], ah[rt], bh + 2);
                mma16(acc[rt][2 * p + 1], ah[rt], br + 2);
                mma16(acc[rt][2 * p + 1], ar[rt], bh + 2);
            }
        }
    }

    const int g = lane >> 2, tg = lane & 3;
    #pragma unroll
    for (int rt = 0; rt < 2; rt++) {
        #pragma unroll
        for (int n2 = 0; n2 < 8; n2++) {
            int gr = row0 + w * 32 + rt * 16 + g;
            int gc = n2 * 8 + tg * 2;
            float* c = acc[rt][n2];
            float* p0 = C + (long)gr * ldc + gc;
            float* p1 = p0 + 8 * (long)ldc;
            if (kSplit > 1) {
                atomicAdd(p0 + 0, alpha * c[0]); atomicAdd(p0 + 1, alpha * c[1]);
                atomicAdd(p1 + 0, alpha * c[2]); atomicAdd(p1 + 1, alpha * c[3]);
            } else {
                p0[0] = alpha * c[0]; p0[1] = alpha * c[1];
                p1[0] = alpha * c[2]; p1[1] = alpha * c[3];
            }
        }
    }
}

static void gemmH64(int M, int K, float alpha,
                    const float* A, int lda, long sA,
                    const float* B, int ldb, long sB,
                    float* C, int ldc, long sC, int batch, int kSplit,
                    const float* brs = nullptr)
{
    dim3 g(1, M / 128, batch * kSplit);
    gemmH64_k<<<g, 128>>>(M, K, alpha, A, lda, sA, B, ldb, sB,
                          C, ldc, sC, kSplit, brs);
}

// =====================================================================
// gemmHP: fp16x2 pinv GEMM (measured). 64x64 CTA, batched 256x256.
// =====================================================================
static const int PROWB  = 48;
static const int PPLANE = 64 * PROWB;
static const int PBUF   = 4 * PPLANE;
__global__ __launch_bounds__(128, 3)
void gemmHP_k(float alpha, float diag,
              const float* __restrict__ A, const float* __restrict__ B,
              float* __restrict__ C, float* __restrict__ CT,
              float alpha2, float diag2,
              float* __restrict__ C2, float* __restrict__ C2T)
{
    __shared__ __align__(16) char smem[2 * PBUF];

    const long sb = (long)MLAND * MLAND;
    A += blockIdx.z * sb; B += blockIdx.z * sb; C += blockIdx.z * sb;
    if (CT)  CT  += blockIdx.z * sb;
    if (C2)  C2  += blockIdx.z * sb;
    if (C2T) C2T += blockIdx.z * sb;

    const int row0 = blockIdx.y * 64;
    const int col0 = blockIdx.x * 64;
    const int tid  = threadIdx.x;
    const int lane = tid & 31, w = tid >> 5, wr = w >> 1, wc = w & 1;

    const int  sr    = tid & 63;
    const bool isB   = tid >= 64;
    const float* src = isB ? (B + (long)(col0 + sr) * MLAND)
                           : (A + (long)(row0 + sr) * MLAND);
    const unsigned stOff = (isB ? 2 * PPLANE : 0) + sr * PROWB;

    unsigned aLd[2];
    #pragma unroll
    for (int rt = 0; rt < 2; rt++) {
        int rrow = wr * 32 + rt * 16 + (lane & 15);
        aLd[rt] = sptr(smem + rrow * PROWB + (lane >> 4) * 16);
    }
    unsigned bLd[2];
    #pragma unroll
    for (int p = 0; p < 2; p++) {
        int n = wc * 32 + p * 16 + (lane & 7) + ((lane & 16) >> 1);
        bLd[p] = sptr(smem + 2 * PPLANE + n * PROWB + ((lane >> 3) & 1) * 16);
    }

    float acc[2][4][4];
    #pragma unroll
    for (int i = 0; i < 2; i++)
        #pragma unroll
        for (int j = 0; j < 4; j++)
            #pragma unroll
            for (int v = 0; v < 4; v++) acc[i][j][v] = 0.f;

    const int CH = MLAND >> 4;
    float4 p0, p1, p2, p3;
    auto loadRegs = [&](int c) {
        const float* s = src + c * 16;
        p0 = *(const float4*)(s);     p1 = *(const float4*)(s + 4);
        p2 = *(const float4*)(s + 8); p3 = *(const float4*)(s + 12);
    };
    auto stsAll = [&](int b) {
        unsigned off = b * PBUF + stOff;
        uint4 h, r;
        packsplit8(p0, p1, h, r);
        *(uint4*)(smem + off)               = h;
        *(uint4*)(smem + off + PPLANE)      = r;
        packsplit8(p2, p3, h, r);
        *(uint4*)(smem + off + 16)          = h;
        *(uint4*)(smem + off + PPLANE + 16) = r;
    };

    loadRegs(0);
    for (int c = 0; c < CH; c++) {
        int b = c & 1;
        stsAll(b);
        if (c + 1 < CH) loadRegs(c + 1);
        __syncthreads();
        unsigned off = b * PBUF;
        unsigned ah[2][4], ar[2][4];
        #pragma unroll
        for (int rt = 0; rt < 2; rt++) {
            ldsm4(ah[rt][0], ah[rt][1], ah[rt][2], ah[rt][3], aLd[rt] + off);
            ldsm4(ar[rt][0], ar[rt][1], ar[rt][2], ar[rt][3],
                  aLd[rt] + off + PPLANE);
        }
        #pragma unroll
        for (int p = 0; p < 2; p++) {
            unsigned bh[4], br[4];
            ldsm4(bh[0], bh[1], bh[2], bh[3], bLd[p] + off);
            ldsm4(br[0], br[1], br[2], br[3], bLd[p] + off + PPLANE);
            #pragma unroll
            for (int rt = 0; rt < 2; rt++) {
                mma16(acc[rt][2 * p],     ah[rt], bh);
                mma16(acc[rt][2 * p],     ah[rt], br);
                mma16(acc[rt][2 * p],     ar[rt], bh);
                mma16(acc[rt][2 * p + 1], ah[rt], bh + 2);
                mma16(acc[rt][2 * p + 1], ah[rt], br + 2);
                mma16(acc[rt][2 * p + 1], ar[rt], bh + 2);
            }
        }
    }

    const int g = lane >> 2, tg = lane & 3;
    #pragma unroll
    for (int rt = 0; rt < 2; rt++) {
        #pragma unroll
        for (int n2 = 0; n2 < 4; n2++) {
            int gr = row0 + wr * 32 + rt * 16 + g;
            int gc = col0 + wc * 32 + n2 * 8 + tg * 2;
            float* c = acc[rt][n2];
            float d00 = (gr == gc) ? 1.f : 0.f;
            float d01 = (gr == gc + 1) ? 1.f : 0.f;
            float d10 = (gr + 8 == gc) ? 1.f : 0.f;
            float d11 = (gr + 8 == gc + 1) ? 1.f : 0.f;
            float v00 = alpha * c[0] + diag * d00;
            float v01 = alpha * c[1] + diag * d01;
            float v10 = alpha * c[2] + diag * d10;
            float v11 = alpha * c[3] + diag * d11;
            long i0 = (long)gr * MLAND + gc;
            long i1 = i0 + 8 * MLAND;
            C[i0] = v00; C[i0 + 1] = v01;
            C[i1] = v10; C[i1 + 1] = v11;
            if (CT) {
                CT[(long)gc * MLAND + gr]           = v00;
                CT[(long)(gc + 1) * MLAND + gr]     = v01;
                CT[(long)gc * MLAND + gr + 8]       = v10;
                CT[(long)(gc + 1) * MLAND + gr + 8] = v11;
            }
            if (C2) {
                float w00 = alpha2 * c[0] + diag2 * d00;
                float w01 = alpha2 * c[1] + diag2 * d01;
                float w10 = alpha2 * c[2] + diag2 * d10;
                float w11 = alpha2 * c[3] + diag2 * d11;
                C2[i0] = w00; C2[i0 + 1] = w01;
                C2[i1] = w10; C2[i1 + 1] = w11;
                if (C2T) {
                    C2T[(long)gc * MLAND + gr]           = w00;
                    C2T[(long)(gc + 1) * MLAND + gr]     = w01;
                    C2T[(long)gc * MLAND + gr + 8]       = w10;
                    C2T[(long)(gc + 1) * MLAND + gr + 8] = w11;
                }
            }
        }
    }
}

// ---------------- small kernels ----------------
__global__ void transpose_k(const float* __restrict__ S, float* __restrict__ D,
                            int R, int C)
{
    __shared__ float t[32][33];
    int r0 = blockIdx.y * 32, c0 = blockIdx.x * 32;
    int x = threadIdx.x, y0 = threadIdx.y;
    #pragma unroll
    for (int i = y0; i < 32; i += 8)
        t[i][x] = S[(long)(r0 + i) * C + c0 + x];
    __syncthreads();
    #pragma unroll
    for (int i = y0; i < 32; i += 8)
        D[(long)(c0 + i) * R + r0 + x] = t[x][i];
}

__global__ void zeros_k(float* a3v, float* Araw, unsigned int* norm,
                        float* rs1, float* rs3)
{
    long i = (long)blockIdx.x * 256 + threadIdx.x;
    if (i < NHEADS * MLAND * DHEAD) a3v[i] = 0.f;
    if (i < NTOK) Araw[i] = 0.f;
    if (i < 2) norm[i] = 0u;
    if (i < (long)NHEADS * NTOK) rs1[i] = 0.f;
    if (i < NHEADS * MLAND) rs3[i] = 0.f;
}

__global__ void landmarks_k(const float* __restrict__ qkv,
                            float* __restrict__ ql, float* __restrict__ kl)
{
    int idx = blockIdx.x * blockDim.x + threadIdx.x;
    if (idx >= NHEADS * MLAND * DHEAD) return;
    int d = idx & 63; int j = (idx >> 6) & 255; int h = idx >> 14;
    const float* qp = qkv + (long)(j * LFOLD) * QKVW + h * DHEAD + d;
    const float* kp = qp + NHEADS * DHEAD;
    float sq = 0.f, sk = 0.f;
    #pragma unroll 4
    for (int t = 0; t < LFOLD; t++) {
        sq += qp[(long)t * QKVW];
        sk += kp[(long)t * QKVW];
    }
    ql[idx] = sq * (1.f / LFOLD);
    kl[idx] = sk * (1.f / LFOLD);
}

__global__ __launch_bounds__(256)
void softmax256_k(float* __restrict__ X)
{
    float* x = X + (long)blockIdx.x * 256;
    int tid = threadIdx.x;
    __shared__ float sm[8];
    float v = x[tid];
    float m = v;
    #pragma unroll
    for (int o = 16; o; o >>= 1) m = fmaxf(m, __shfl_xor_sync(0xffffffffu, m, o));
    if ((tid & 31) == 0) sm[tid >> 5] = m;
    __syncthreads();
    m = sm[0];
    #pragma unroll
    for (int i = 1; i < 8; i++) m = fmaxf(m, sm[i]);
    float e = __expf(v - m);
    float s = e;
    #pragma unroll
    for (int o = 16; o; o >>= 1) s += __shfl_xor_sync(0xffffffffu, s, o);
    __syncthreads();
    if ((tid & 31) == 0) sm[tid >> 5] = s;
    __syncthreads();
    s = sm[0];
    #pragma unroll
    for (int i = 1; i < 8; i++) s += sm[i];
    x[tid] = e * (1.f / s);
}

__global__ void a2norm_k(const float* __restrict__ a2, unsigned int* norm)
{
    int h = blockIdx.x; int t = threadIdx.x;
    const float* x = a2 + (long)h * MLAND * MLAND;
    float rs = 0.f, cs = 0.f;
    for (int j = 0; j < MLAND; j++) {
        rs += fabsf(x[t * MLAND + j]);
        cs += fabsf(x[j * MLAND + t]);
    }
    __shared__ float s1[8], s2[8];
    for (int o = 16; o; o >>= 1) {
        rs = fmaxf(rs, __shfl_xor_sync(0xffffffffu, rs, o));
        cs = fmaxf(cs, __shfl_xor_sync(0xffffffffu, cs, o));
    }
    if ((t & 31) == 0) { s1[t >> 5] = rs; s2[t >> 5] = cs; }
    __syncthreads();
    if (t == 0) {
        rs = s1[0]; cs = s2[0];
        for (int w = 1; w < 8; w++) { rs = fmaxf(rs, s1[w]); cs = fmaxf(cs, s2[w]); }
        atomicMax(&norm[0], __float_as_uint(rs));
        atomicMax(&norm[1], __float_as_uint(cs));
    }
}

// writes z = a2^T * inv  AND  zT = a2 * inv
__global__ void zinit2_k(const float* __restrict__ a2, float* __restrict__ z,
                         float* __restrict__ zT,
                         const unsigned int* __restrict__ norm)
{
    long idx = (long)blockIdx.x * 256 + threadIdx.x;
    if (idx >= (long)NHEADS * MLAND * MLAND) return;
    float inv = 1.f / (__uint_as_float(norm[0]) * __uint_as_float(norm[1]));
    int j = idx & 255; int i = (idx >> 8) & 255; long h = idx >> 16;
    z[idx]  = a2[h * 65536 + (long)j * 256 + i] * inv;
    zT[idx] = a2[idx] * inv;
}

// conv + fold 1/rowsum(a1) into xh:  xh = xh*inv + conv(v)
__global__ __launch_bounds__(256)
void convadd2_k(const float* __restrict__ qkv,
                const float* __restrict__ rker,
                float* __restrict__ xh,
                const float* __restrict__ rs1)
{
    __shared__ float skr[NHEADS * KCONV];
    for (int i = threadIdx.x; i < NHEADS * KCONV; i += 256) skr[i] = rker[i];
    __syncthreads();
    int idx = blockIdx.x * 256 + threadIdx.x;
    int col = idx & 511;
    int ng = idx >> 9;
    if (ng >= NTOK / 8) return;
    long n0 = (long)ng * 8;
    int h = col >> 6;
    const float* kr = skr + h * KCONV;
    const float* v = qkv + 2 * NHEADS * DHEAD + col;
    const float* rsb = rs1 + (long)h * NTOK;
    float win[40];
    #pragma unroll
    for (int j = 0; j < 40; j++) {
        long r = n0 - 16 + j;
        win[j] = (r >= 0 && r < NTOK) ? v[r * QKVW] : 0.f;
    }
    #pragma unroll
    for (int i = 0; i < 8; i++) {
        float s = 0.f;
        #pragma unroll
        for (int t = 0; t < KCONV; t++) s += kr[t] * win[i + t];
        long o = (n0 + i) * DMODEL + col;
        xh[o] = xh[o] / rsb[n0 + i] + s;
    }
}

__global__ void edge_k(const float* __restrict__ qeke,
                       const int* __restrict__ rows, const int* __restrict__ cols,
                       const float* __restrict__ vals, float* __restrict__ Araw)
{
    int e = blockIdx.x * (blockDim.x >> 5) + (threadIdx.x >> 5);
    int lane = threadIdx.x & 31;
    if (e >= NEDGE) return;
    int r = rows[e], c = cols[e];
    const float4* qr = (const float4*)(qeke + (long)r * 512);
    const float4* kc = (const float4*)(qeke + (long)c * 512 + WPD);
    float s = 0.f;
    #pragma unroll
    for (int i = lane; i < WPD / 4; i += 32) {
        float4 a = qr[i], b = kc[i];
        s += a.x * b.x + a.y * b.y + a.z * b.z + a.w * b.w;
    }
    for (int o = 16; o; o >>= 1) s += __shfl_xor_sync(0xffffffffu, s, o);
    if (lane == 0) atomicAdd(&Araw[r], s * 0.0625f * vals[e]);
}

// softmax over all N + copy Araw into the output tail
__global__ void softmax_all_k(const float* __restrict__ A, float* __restrict__ alpha,
                              int n, float* __restrict__ outTail)
{
    __shared__ float sm[32];
    int tid = threadIdx.x;
    float m = -1e30f;
    for (int i = tid; i < n; i += 1024) m = fmaxf(m, A[i]);
    for (int o = 16; o; o >>= 1) m = fmaxf(m, __shfl_xor_sync(0xffffffffu, m, o));
    if ((tid & 31) == 0) sm[tid >> 5] = m;
    __syncthreads();
    if (tid == 0) { float bm = sm[0]; for (int w = 1; w < 32; w++) bm = fmaxf(bm, sm[w]); sm[0] = bm; }
    __syncthreads();
    m = sm[0];
    __syncthreads();
    float s = 0.f;
    for (int i = tid; i < n; i += 1024) s += __expf(A[i] - m);
    for (int o = 16; o; o >>= 1) s += __shfl_xor_sync(0xffffffffu, s, o);
    if ((tid & 31) == 0) sm[tid >> 5] = s;
    __syncthreads();
    if (tid == 0) { float bs = 0.f; for (int w = 0; w < 32; w++) bs += sm[w]; sm[0] = bs; }
    __syncthreads();
    float inv = 1.f / sm[0];
    for (int i = tid; i < n; i += 1024) {
        float a = A[i];
        alpha[i] = __expf(a - m) * inv;
        outTail[i] = a;
    }
}

// ---------------- driver ----------------
extern "C" void kernel_launch(void* const* d_in, const int* in_sizes, int n_in,
                              void* d_out, int out_size)
{
    const float* dense  = (const float*)d_in[0];
    const int*   arows  = (const int*)  d_in[1];
    const int*   acols  = (const int*)  d_in[2];
    const float* avals  = (const float*)d_in[3];
    const float* wq     = (const float*)d_in[4];
    const float* wk     = (const float*)d_in[5];
    const float* w_qkv  = (const float*)d_in[6];
    const float* w_out  = (const float*)d_in[7];
    const float* b_out  = (const float*)d_in[8];
    const float* rker   = (const float*)d_in[9];
    const float* wv_w   = (const float*)d_in[10];
    const float* wv_b   = (const float*)d_in[11];
    float* out = (float*)d_out;

    float *qkv, *ql, *kl, *a1, *a2, *a3, *z, *zT, *z2, *z2T, *xz;
    float *t1, *t1T, *t2, *t2T, *a3v, *zv;
    float *xh, *enc, *qeke, *wqkT, *rs1, *rs3, *Araw, *alpha;
    unsigned int* norm;
    cudaGetSymbolAddress((void**)&qkv, g_qkv);
    cudaGetSymbolAddress((void**)&ql,  g_ql);
    cudaGetSymbolAddress((void**)&kl,  g_kl);
    cudaGetSymbolAddress((void**)&a1,  g_a1);
    cudaGetSymbolAddress((void**)&a2,  g_a2);
    cudaGetSymbolAddress((void**)&a3,  g_a3);
    cudaGetSymbolAddress((void**)&z,   g_z);
    cudaGetSymbolAddress((void**)&zT,  g_zT);
    cudaGetSymbolAddress((void**)&z2,  g_z2);
    cudaGetSymbolAddress((void**)&z2T, g_z2T);
    cudaGetSymbolAddress((void**)&xz,  g_xz);
    cudaGetSymbolAddress((void**)&t1,  g_t1);
    cudaGetSymbolAddress((void**)&t1T, g_t1T);
    cudaGetSymbolAddress((void**)&t2,  g_t2);
    cudaGetSymbolAddress((void**)&t2T, g_t2T);
    cudaGetSymbolAddress((void**)&a3v, g_a3v);
    cudaGetSymbolAddress((void**)&zv,  g_zv);
    cudaGetSymbolAddress((void**)&xh,  g_xh);
    cudaGetSymbolAddress((void**)&enc, g_enc);
    cudaGetSymbolAddress((void**)&qeke, g_qeke);
    cudaGetSymbolAddress((void**)&wqkT, g_wqkT);
    cudaGetSymbolAddress((void**)&rs1, g_rs1);
    cudaGetSymbolAddress((void**)&rs3, g_rs3);
    cudaGetSymbolAddress((void**)&Araw, g_Araw);
    cudaGetSymbolAddress((void**)&alpha, g_alpha);
    cudaGetSymbolAddress((void**)&norm, g_norm);

    const float qscale = 0.125f;
    const long  smm    = (long)MLAND * MLAND;

    // 0. zero scratch (grid MUST cover a3v: 131072 elems = 512 blocks)
    zeros_k<<<(NHEADS * MLAND * DHEAD + 255) / 256, 256>>>(a3v, Araw, norm, rs1, rs3);
    {
        dim3 b(32, 8);
        transpose_k<<<dim3(WPD / 32, DMODEL / 32), b>>>(wq, wqkT, DMODEL, WPD);
        transpose_k<<<dim3(WPD / 32, DMODEL / 32), b>>>(wk, wqkT + WPD * DMODEL,
                                                        DMODEL, WPD);
    }

    // 1. qkv = dense @ w_qkv^T  [8192,1536]
    gemmH(NTOK, QKVW, DMODEL, 1.f, dense, DMODEL, 0, w_qkv, DMODEL, 0,
          qkv, QKVW, 0, 1);

    // 2. landmarks
    landmarks_k<<<(NHEADS * MLAND * DHEAD + 255) / 256, 256>>>(qkv, ql, kl);

    // 3. a1 = exp(scale * q @ k_l^T) (unnormalized, rowsums -> rs1)
    gemmH(NTOK, MLAND, DHEAD, qscale,
          qkv, QKVW, DHEAD, kl, DHEAD, (long)MLAND * DHEAD,
          a1, MLAND, (long)NTOK * MLAND, NHEADS, nullptr, nullptr, 1, rs1);

    // 4. a2 = softmax(scale * q_l @ k_l^T) [h,256,256]
    gemmH(MLAND, MLAND, DHEAD, qscale,
          ql, DHEAD, (long)MLAND * DHEAD, kl, DHEAD, (long)MLAND * DHEAD,
          a2, MLAND, smm, NHEADS);
    softmax256_k<<<NHEADS * MLAND, 256>>>(a2);

    // 5. pinv init: z = a2^T/norm, zT = a2/norm
    a2norm_k<<<NHEADS, 256>>>(a2, norm);
    zinit2_k<<<(int)((NHEADS * smm + 255) / 256), 256>>>(a2, z, zT, norm);

    // 6. pinv iterations (fp16x2, fused diag + transposed outputs)
    float *zin = z, *zinT = zT, *zout = z2, *zoutT = z2T;
    dim3 gp(4, 4, NHEADS);
    for (int it = 0; it < PITERS; it++) {
        gemmHP_k<<<gp, 128>>>(1.f, 0.f, a2, zinT, xz, nullptr,
                              -1.f, 7.f, t1, t1T);
        gemmHP_k<<<gp, 128>>>(-1.f, 15.f, xz, t1T, t2, t2T,
                              0.f, 0.f, nullptr, nullptr);
        gemmHP_k<<<gp, 128>>>(-1.f, 13.f, xz, t2T, t1, t1T,
                              0.f, 0.f, nullptr, nullptr);
        gemmHP_k<<<gp, 128>>>(0.25f, 0.f, zin, t1T, zout, zoutT,
                              0.f, 0.f, nullptr, nullptr);
        float* tmp;
        tmp = zin;  zin = zout;   zout = tmp;
        tmp = zinT; zinT = zoutT; zoutT = tmp;
    }
    float* zfin = zin;

    // 7. a3 = exp(scale * q_l @ k^T) (unnormalized, rowsums -> rs3)
    gemmH(MLAND, NTOK, DHEAD, qscale,
          ql, DHEAD, (long)MLAND * DHEAD,
          qkv + NHEADS * DHEAD, QKVW, DHEAD,
          a3, NTOK, (long)MLAND * NTOK, NHEADS, nullptr, nullptr, 1, rs3);

    // 8. a3v = a3exp @ v  [h,256,64]  (split-K 16, atomic; pre-zeroed)
    gemmH64(MLAND, NTOK, 1.f,
            a3, NTOK, (long)MLAND * NTOK,
            qkv + 2 * NHEADS * DHEAD, QKVW, DHEAD,
            a3v, DHEAD, (long)MLAND * DHEAD, NHEADS, 16);

    // 9. zv = zfin @ (a3v rows / rs3)  [h,256,64]  (softmax norm folded)
    gemmH64(MLAND, MLAND, 1.f,
            zfin, MLAND, smm,
            a3v, DHEAD, (long)MLAND * DHEAD,
            zv, DHEAD, (long)MLAND * DHEAD, NHEADS, 1, rs3);

    // 10. xh_un = a1exp @ zv   (a1 norm folded into convadd2)
    gemmH64(NTOK, MLAND, 1.f,
            a1, MLAND, (long)NTOK * MLAND,
            zv, DHEAD, (long)MLAND * DHEAD,
            xh, DMODEL, DHEAD, NHEADS, 1);

    // 11. xh = xh/rs1 + depthwise conv(v)
    convadd2_k<<<(NTOK / 8) * DMODEL / 256, 256>>>(qkv, rker, xh, rs1);

    // 12. enc = xh @ w_out^T + b_out + dense  (fused epilogue)
    gemmH(NTOK, DMODEL, DMODEL, 1.f, xh, DMODEL, 0, w_out, DMODEL, 0,
          enc, DMODEL, 0, 1, dense, b_out);

    // 13. qeke = enc @ [wq|wk]  (single N=512 GEMM)
    gemmH(NTOK, 2 * WPD, DMODEL, 1.f, enc, DMODEL, 0, wqkT, DMODEL, 0,
          qeke, 2 * WPD, 0, 1);

    // 14. edge scores -> segment sum
    edge_k<<<(NEDGE + 7) / 8, 256>>>(qeke, arows, acols, avals, Araw);

    // 15. alpha = softmax(A_raw); also write A_raw output tail
    softmax_all_k<<<1, 1024>>>(Araw, alpha, NTOK, out + (long)NTOK * DMODEL);

    // 16+17. out = gated_blend(alpha * (dense @ wv_w^T + wv_b), enc)
    //        (final fused into the val GEMM epilogue)
    gemmH(NTOK, DMODEL, DMODEL, 1.f, dense, DMODEL, 0, wv_w, DMODEL, 0,
          out, DMODEL, 0, 1, enc, wv_b, 0, nullptr, alpha);
}